// round 7
// baseline (speedup 1.0000x reference)
#include <cuda_runtime.h>
#include <cuda_bf16.h>
#include <cstdint>

#define N_NODES 50000
#define N_EDGES 600000
#define F 128
#define NB_SCAN 196   // ceil(50000/256)

// ---------------- scratch (static device globals; no runtime allocation) ----
__device__ float g_mean[N_NODES * F];
__device__ float g_t[N_NODES * F];     // self-term partial (X@Ws + b)
__device__ float g_h1[N_NODES * F];
__device__ float g_h2[N_NODES * F];
__device__ int   g_rowptr[N_NODES + 1];
__device__ int   g_cursor[N_NODES];
__device__ float g_invdeg[N_NODES];
__device__ int   g_csrsrc[N_EDGES];
__device__ int   g_bsum[NB_SCAN];
__device__ int   g_boff[NB_SCAN];

// ---------------- streams/events (created pre-main, before mem checkpoints) -
struct StreamInit {
    cudaStream_t side;
    cudaEvent_t ev_fork, ev_s1, ev_h1, ev_s2, ev_h2, ev_s3;
    StreamInit() {
        cudaStreamCreateWithFlags(&side, cudaStreamNonBlocking);
        cudaEventCreateWithFlags(&ev_fork, cudaEventDisableTiming);
        cudaEventCreateWithFlags(&ev_s1, cudaEventDisableTiming);
        cudaEventCreateWithFlags(&ev_h1, cudaEventDisableTiming);
        cudaEventCreateWithFlags(&ev_s2, cudaEventDisableTiming);
        cudaEventCreateWithFlags(&ev_h2, cudaEventDisableTiming);
        cudaEventCreateWithFlags(&ev_s3, cudaEventDisableTiming);
    }
};
static StreamInit g_si;

// ---------------- CSR build -------------------------------------------------
__global__ void zero_counts_kernel() {
    int i = blockIdx.x * blockDim.x + threadIdx.x;
    if (i < N_NODES) g_cursor[i] = 0;
}

__global__ void count_kernel(const int* __restrict__ dst) {
    int e = blockIdx.x * blockDim.x + threadIdx.x;
    if (e < N_EDGES) atomicAdd(&g_cursor[dst[e]], 1);
}

// Parallel scan: A (block-local) -> B (block sums) -> C (apply)
__global__ void scanA_kernel() {
    int i = blockIdx.x * 256 + threadIdx.x;
    int c = (i < N_NODES) ? g_cursor[i] : 0;
    __shared__ int s[256];
    s[threadIdx.x] = c;
    __syncthreads();
#pragma unroll
    for (int off = 1; off < 256; off <<= 1) {
        int v = (threadIdx.x >= off) ? s[threadIdx.x - off] : 0;
        __syncthreads();
        s[threadIdx.x] += v;
        __syncthreads();
    }
    int incl = s[threadIdx.x];
    if (i < N_NODES) {
        g_rowptr[i] = incl - c;
        g_invdeg[i] = 1.0f / (float)(c > 1 ? c : 1);
    }
    if (threadIdx.x == 255) g_bsum[blockIdx.x] = incl;
}

__global__ void scanB_kernel() {
    int b = threadIdx.x;
    int v = (b < NB_SCAN) ? g_bsum[b] : 0;
    __shared__ int s[256];
    s[b] = v;
    __syncthreads();
#pragma unroll
    for (int off = 1; off < 256; off <<= 1) {
        int w = (b >= off) ? s[b - off] : 0;
        __syncthreads();
        s[b] += w;
        __syncthreads();
    }
    if (b < NB_SCAN) g_boff[b] = s[b] - v;
    if (b == 0) g_rowptr[N_NODES] = s[NB_SCAN - 1];
}

__global__ void scanC_kernel() {
    int i = blockIdx.x * 256 + threadIdx.x;
    if (i < N_NODES) {
        int r = g_rowptr[i] + g_boff[blockIdx.x];
        g_rowptr[i] = r;
        g_cursor[i] = r;
    }
}

__global__ void fill_kernel(const int* __restrict__ src, const int* __restrict__ dst) {
    int e = blockIdx.x * blockDim.x + threadIdx.x;
    if (e < N_EDGES) {
        int d = dst[e];
        int pos = atomicAdd(&g_cursor[d], 1);
        g_csrsrc[pos] = src[e];
    }
}

// ---------------- neighbor mean aggregation (warp per node) -----------------
__global__ void aggregate_kernel(const float* __restrict__ x) {
    int warp = (blockIdx.x * blockDim.x + threadIdx.x) >> 5;
    int lane = threadIdx.x & 31;
    if (warp >= N_NODES) return;

    int beg = g_rowptr[warp];
    int end = g_rowptr[warp + 1];

    float4 acc = make_float4(0.f, 0.f, 0.f, 0.f);
    for (int i = beg; i < end; i++) {
        int s = __ldg(&g_csrsrc[i]);
        float4 v = *(const float4*)&x[(size_t)s * F + lane * 4];
        acc.x += v.x; acc.y += v.y; acc.z += v.z; acc.w += v.w;
    }
    float inv = g_invdeg[warp];
    float4 o = make_float4(acc.x * inv, acc.y * inv, acc.z * inv, acc.w * inv);
    *(float4*)&g_mean[(size_t)warp * F + lane * 4] = o;
}

// ---------------- tf32 helpers ----------------------------------------------
__device__ __forceinline__ uint32_t f2tf(float x) {
    uint32_t r;
    asm("cvt.rna.tf32.f32 %0, %1;" : "=r"(r) : "f"(x));
    return r;
}

__device__ __forceinline__ void mma_tf32(float* c, const uint32_t* a, const uint32_t* b) {
    asm volatile(
        "mma.sync.aligned.m16n8k8.row.col.f32.tf32.tf32.f32 "
        "{%0,%1,%2,%3}, {%4,%5,%6,%7}, {%8,%9}, {%0,%1,%2,%3};"
        : "+f"(c[0]), "+f"(c[1]), "+f"(c[2]), "+f"(c[3])
        : "r"(a[0]), "r"(a[1]), "r"(a[2]), "r"(a[3]),
          "r"(b[0]), "r"(b[1]));
}

#define PADA 36
#define PADB 136

// ---------------- single-term tf32 GEMM core (K=128) ------------------------
// MODE 0 (self):  out = A@W + bias          (no relu)
// MODE 1 (neigh): out = A@W + addfrom [+relu]
template <int MODE>
__global__ __launch_bounds__(256, 2) void gemm_half_tf32(
    const float* __restrict__ A,
    const float* __restrict__ W,
    const float* __restrict__ bias,      // MODE 0
    const float* __restrict__ addfrom,   // MODE 1
    float* __restrict__ out, int do_relu)
{
    __shared__ uint32_t As[128 * PADA];
    __shared__ uint32_t Bs[32 * PADB];

    const int tid  = threadIdx.x;
    const int lane = tid & 31;
    const int wid  = tid >> 5;
    const int wm   = wid & 1;
    const int wn   = wid >> 1;
    const int g    = lane >> 2;
    const int tig  = lane & 3;
    const int bm   = blockIdx.x * 128;

    float c[4][4][4];
#pragma unroll
    for (int mi = 0; mi < 4; mi++)
#pragma unroll
        for (int ni = 0; ni < 4; ni++)
#pragma unroll
            for (int r = 0; r < 4; r++) c[mi][ni][r] = 0.f;

    float4 pa[4], pb[4];
    // preload chunk 0
#pragma unroll
    for (int i = 0; i < 4; i++) {
        int slot = tid + 256 * i;
        int r    = slot >> 3;
        int kq   = slot & 7;
        int grow = bm + r;
        pa[i] = make_float4(0.f, 0.f, 0.f, 0.f);
        if (grow < N_NODES)
            pa[i] = *(const float4*)&A[(size_t)grow * F + kq * 4];
        int kr = slot >> 5;
        int nb = (slot & 31) * 4;
        pb[i] = *(const float4*)&W[(size_t)kr * F + nb];
    }

    for (int kc = 0; kc < 4; ++kc) {
#pragma unroll
        for (int i = 0; i < 4; i++) {
            int slot = tid + 256 * i;
            int r    = slot >> 3;
            int kq   = slot & 7;
            uint32_t* p = &As[r * PADA + kq * 4];
            p[0] = f2tf(pa[i].x); p[1] = f2tf(pa[i].y);
            p[2] = f2tf(pa[i].z); p[3] = f2tf(pa[i].w);
            int kr = slot >> 5;
            int nb = (slot & 31) * 4;
            uint32_t* q = &Bs[kr * PADB + nb];
            q[0] = f2tf(pb[i].x); q[1] = f2tf(pb[i].y);
            q[2] = f2tf(pb[i].z); q[3] = f2tf(pb[i].w);
        }
        __syncthreads();

        if (kc < 3) {
            const int k0n = (kc + 1) * 32;
#pragma unroll
            for (int i = 0; i < 4; i++) {
                int slot = tid + 256 * i;
                int r    = slot >> 3;
                int kq   = slot & 7;
                int grow = bm + r;
                pa[i] = make_float4(0.f, 0.f, 0.f, 0.f);
                if (grow < N_NODES)
                    pa[i] = *(const float4*)&A[(size_t)grow * F + k0n + kq * 4];
                int kr = slot >> 5;
                int nb = (slot & 31) * 4;
                pb[i] = *(const float4*)&W[(size_t)(k0n + kr) * F + nb];
            }
        }

#pragma unroll
        for (int ks = 0; ks < 4; ++ks) {
            uint32_t a[4][4];
            uint32_t b[4][2];
#pragma unroll
            for (int mi = 0; mi < 4; mi++) {
                int r0 = wm * 64 + mi * 16 + g;
                a[mi][0] = As[r0 * PADA + ks * 8 + tig];
                a[mi][1] = As[(r0 + 8) * PADA + ks * 8 + tig];
                a[mi][2] = As[r0 * PADA + ks * 8 + tig + 4];
                a[mi][3] = As[(r0 + 8) * PADA + ks * 8 + tig + 4];
            }
#pragma unroll
            for (int ni = 0; ni < 4; ni++) {
                int cb = wn * 32 + ni * 8 + g;
                b[ni][0] = Bs[(ks * 8 + tig) * PADB + cb];
                b[ni][1] = Bs[(ks * 8 + tig + 4) * PADB + cb];
            }
#pragma unroll
            for (int mi = 0; mi < 4; mi++)
#pragma unroll
                for (int ni = 0; ni < 4; ni++)
                    mma_tf32(c[mi][ni], a[mi], b[ni]);
        }
        __syncthreads();
    }

    // ---- epilogue
#pragma unroll
    for (int mi = 0; mi < 4; mi++) {
        int row0 = bm + wm * 64 + mi * 16 + g;
#pragma unroll
        for (int ni = 0; ni < 4; ni++) {
            int col = wn * 32 + ni * 8 + tig * 2;
            float2 add0, add1;
            if (MODE == 0) {
                add0 = *(const float2*)&bias[col];
                add1 = add0;
            } else {
                add0 = make_float2(0.f, 0.f);
                add1 = make_float2(0.f, 0.f);
                if (row0 < N_NODES)
                    add0 = *(const float2*)&addfrom[(size_t)row0 * F + col];
                if (row0 + 8 < N_NODES)
                    add1 = *(const float2*)&addfrom[(size_t)(row0 + 8) * F + col];
            }
            float2 o0, o1;
            o0.x = c[mi][ni][0] + add0.x;
            o0.y = c[mi][ni][1] + add0.y;
            o1.x = c[mi][ni][2] + add1.x;
            o1.y = c[mi][ni][3] + add1.y;
            if (MODE == 1 && do_relu) {
                o0.x = fmaxf(o0.x, 0.f); o0.y = fmaxf(o0.y, 0.f);
                o1.x = fmaxf(o1.x, 0.f); o1.y = fmaxf(o1.y, 0.f);
            }
            if (row0 < N_NODES)
                *(float2*)&out[(size_t)row0 * F + col] = o0;
            if (row0 + 8 < N_NODES)
                *(float2*)&out[(size_t)(row0 + 8) * F + col] = o1;
        }
    }
}

// ---------------- launch ----------------------------------------------------
extern "C" void kernel_launch(void* const* d_in, const int* in_sizes, int n_in,
                              void* d_out, int out_size)
{
    const float* feat = (const float*)d_in[0];
    const int*   src  = (const int*)d_in[1];
    const int*   dst  = (const int*)d_in[2];
    const float* W1s = (const float*)d_in[3];
    const float* W1n = (const float*)d_in[4];
    const float* b1  = (const float*)d_in[5];
    const float* W2s = (const float*)d_in[6];
    const float* W2n = (const float*)d_in[7];
    const float* b2  = (const float*)d_in[8];
    const float* W3s = (const float*)d_in[9];
    const float* W3n = (const float*)d_in[10];
    const float* b3  = (const float*)d_in[11];
    float* out = (float*)d_out;

    void* p;
    cudaGetSymbolAddress(&p, g_h1);   float* h1   = (float*)p;
    cudaGetSymbolAddress(&p, g_h2);   float* h2   = (float*)p;
    cudaGetSymbolAddress(&p, g_mean); float* mean = (float*)p;
    cudaGetSymbolAddress(&p, g_t);    float* t    = (float*)p;

    const int TB = 256;
    const int agg_grid  = (N_NODES + 7) / 8;
    const int gemm_grid = (N_NODES + 127) / 128;
    cudaStream_t side = g_si.side;

    // fork side stream into capture
    cudaEventRecord(g_si.ev_fork, 0);
    cudaStreamWaitEvent(side, g_si.ev_fork, 0);

    // side: self-term of layer 1 (overlaps entire CSR build)
    gemm_half_tf32<0><<<gemm_grid, TB, 0, side>>>(feat, W1s, b1, nullptr, t, 0);
    cudaEventRecord(g_si.ev_s1, side);

    // main: CSR build
    zero_counts_kernel<<<(N_NODES + TB - 1) / TB, TB>>>();
    count_kernel<<<(N_EDGES + TB - 1) / TB, TB>>>(dst);
    scanA_kernel<<<NB_SCAN, 256>>>();
    scanB_kernel<<<1, 256>>>();
    scanC_kernel<<<NB_SCAN, 256>>>();
    fill_kernel<<<(N_EDGES + TB - 1) / TB, TB>>>(src, dst);

    // layer 1
    aggregate_kernel<<<agg_grid, TB>>>(feat);
    cudaStreamWaitEvent(0, g_si.ev_s1, 0);
    gemm_half_tf32<1><<<gemm_grid, TB>>>(mean, W1n, nullptr, t, h1, 1);
    cudaEventRecord(g_si.ev_h1, 0);

    // layer 2: self on side stream overlaps aggregate
    cudaStreamWaitEvent(side, g_si.ev_h1, 0);
    gemm_half_tf32<0><<<gemm_grid, TB, 0, side>>>(h1, W2s, b2, nullptr, t, 0);
    cudaEventRecord(g_si.ev_s2, side);
    aggregate_kernel<<<agg_grid, TB>>>(h1);
    cudaStreamWaitEvent(0, g_si.ev_s2, 0);
    gemm_half_tf32<1><<<gemm_grid, TB>>>(mean, W2n, nullptr, t, h2, 1);
    cudaEventRecord(g_si.ev_h2, 0);

    // layer 3
    cudaStreamWaitEvent(side, g_si.ev_h2, 0);
    gemm_half_tf32<0><<<gemm_grid, TB, 0, side>>>(h2, W3s, b3, nullptr, t, 0);
    cudaEventRecord(g_si.ev_s3, side);
    aggregate_kernel<<<agg_grid, TB>>>(h2);
    cudaStreamWaitEvent(0, g_si.ev_s3, 0);
    gemm_half_tf32<1><<<gemm_grid, TB>>>(mean, W3n, nullptr, t, out, 0);
}

// round 9
// speedup vs baseline: 1.1123x; 1.1123x over previous
#include <cuda_runtime.h>
#include <cuda_bf16.h>
#include <cuda_fp16.h>
#include <cstdint>

#define N_NODES 50000
#define N_EDGES 600000
#define F 128
#define NB_SCAN 196   // ceil(50000/256)

// ---------------- scratch (static device globals; no runtime allocation) ----
__device__ float  g_mean[N_NODES * F];
__device__ float  g_h1[N_NODES * F];
__device__ float  g_h2[N_NODES * F];
__device__ __half g_x16[N_NODES * F];   // fp16 copy of current layer input
__device__ int    g_rowptr[N_NODES + 1];
__device__ int    g_cursor[N_NODES];
__device__ float  g_invdeg[N_NODES];
__device__ int    g_csrsrc[N_EDGES];
__device__ int    g_bsum[NB_SCAN];
__device__ int    g_boff[NB_SCAN];

// ---------------- CSR build -------------------------------------------------
__global__ void count_kernel(const int* __restrict__ dst) {
    int e = blockIdx.x * blockDim.x + threadIdx.x;
    if (e < N_EDGES) atomicAdd(&g_cursor[dst[e]], 1);
}

// Parallel scan: A (block-local) -> B (block sums) -> C (apply)
__global__ void scanA_kernel() {
    int i = blockIdx.x * 256 + threadIdx.x;
    int c = (i < N_NODES) ? g_cursor[i] : 0;
    __shared__ int s[256];
    s[threadIdx.x] = c;
    __syncthreads();
#pragma unroll
    for (int off = 1; off < 256; off <<= 1) {
        int v = (threadIdx.x >= off) ? s[threadIdx.x - off] : 0;
        __syncthreads();
        s[threadIdx.x] += v;
        __syncthreads();
    }
    int incl = s[threadIdx.x];
    if (i < N_NODES) {
        g_rowptr[i] = incl - c;
        g_invdeg[i] = 1.0f / (float)(c > 1 ? c : 1);
    }
    if (threadIdx.x == 255) g_bsum[blockIdx.x] = incl;
}

__global__ void scanB_kernel() {
    int b = threadIdx.x;
    int v = (b < NB_SCAN) ? g_bsum[b] : 0;
    __shared__ int s[256];
    s[b] = v;
    __syncthreads();
#pragma unroll
    for (int off = 1; off < 256; off <<= 1) {
        int w = (b >= off) ? s[b - off] : 0;
        __syncthreads();
        s[b] += w;
        __syncthreads();
    }
    if (b < NB_SCAN) g_boff[b] = s[b] - v;
    if (b == 0) g_rowptr[N_NODES] = s[NB_SCAN - 1];
}

__global__ void scanC_kernel() {
    int i = blockIdx.x * 256 + threadIdx.x;
    if (i < N_NODES) {
        int r = g_rowptr[i] + g_boff[blockIdx.x];
        g_rowptr[i] = r;
        g_cursor[i] = r;
    }
}

__global__ void fill_kernel(const int* __restrict__ src, const int* __restrict__ dst) {
    int e = blockIdx.x * blockDim.x + threadIdx.x;
    if (e < N_EDGES) {
        int d = dst[e];
        int pos = atomicAdd(&g_cursor[d], 1);
        g_csrsrc[pos] = src[e];
    }
}

// ---------------- fp32 -> fp16 convert (layer-1 input) ----------------------
__global__ void convert_kernel(const float* __restrict__ x, __half* __restrict__ x16) {
    int i = blockIdx.x * blockDim.x + threadIdx.x;
    if (i < N_NODES * F / 4) {
        float4 v = *(const float4*)&x[(size_t)i * 4];
        __half2 h0 = __floats2half2_rn(v.x, v.y);
        __half2 h1 = __floats2half2_rn(v.z, v.w);
        uint2 o;
        o.x = *(uint32_t*)&h0;
        o.y = *(uint32_t*)&h1;
        *(uint2*)&x16[(size_t)i * 4] = o;
    }
}

// ---------------- neighbor mean aggregation (fp16 gather, fp32 accum) -------
__global__ void aggregate16_kernel(const __half* __restrict__ x16) {
    int warp = (blockIdx.x * blockDim.x + threadIdx.x) >> 5;
    int lane = threadIdx.x & 31;
    if (warp >= N_NODES) return;

    int beg = g_rowptr[warp];
    int end = g_rowptr[warp + 1];

    float a0 = 0.f, a1 = 0.f, a2 = 0.f, a3 = 0.f;
    for (int i = beg; i < end; i++) {
        int s = __ldg(&g_csrsrc[i]);
        uint2 v = *(const uint2*)(x16 + (size_t)s * F + lane * 4);
        __half2 h0 = *(__half2*)&v.x;
        __half2 h1 = *(__half2*)&v.y;
        float2 f0 = __half22float2(h0);
        float2 f1 = __half22float2(h1);
        a0 += f0.x; a1 += f0.y; a2 += f1.x; a3 += f1.y;
    }
    float inv = g_invdeg[warp];
    float4 o = make_float4(a0 * inv, a1 * inv, a2 * inv, a3 * inv);
    *(float4*)&g_mean[(size_t)warp * F + lane * 4] = o;
}

// ---------------- tf32 helpers ----------------------------------------------
__device__ __forceinline__ uint32_t f2tf(float x) {
    uint32_t r;
    asm("cvt.rna.tf32.f32 %0, %1;" : "=r"(r) : "f"(x));
    return r;
}

__device__ __forceinline__ void mma_tf32(float* c, const uint32_t* a, const uint32_t* b) {
    asm volatile(
        "mma.sync.aligned.m16n8k8.row.col.f32.tf32.tf32.f32 "
        "{%0,%1,%2,%3}, {%4,%5,%6,%7}, {%8,%9}, {%0,%1,%2,%3};"
        : "+f"(c[0]), "+f"(c[1]), "+f"(c[2]), "+f"(c[3])
        : "r"(a[0]), "r"(a[1]), "r"(a[2]), "r"(a[3]),
          "r"(b[0]), "r"(b[1]));
}

#define PADA 36
#define PADB 136

// ---------------- fused tf32 SAGE GEMM --------------------------------------
// out = X @ Ws + mean @ Wn + b (optional relu); optionally also emits fp16 out.
__global__ __launch_bounds__(256, 2) void gemm_sage_tf32(
    const float* __restrict__ X,
    const float* __restrict__ MEAN,
    const float* __restrict__ Ws, const float* __restrict__ Wn,
    const float* __restrict__ bias,
    float* __restrict__ out, __half* __restrict__ out16, int do_relu)
{
    __shared__ uint32_t As[128 * PADA];
    __shared__ uint32_t Bs[32 * PADB];

    const int tid  = threadIdx.x;
    const int lane = tid & 31;
    const int wid  = tid >> 5;
    const int wm   = wid & 1;
    const int wn   = wid >> 1;
    const int g    = lane >> 2;
    const int tig  = lane & 3;
    const int bm   = blockIdx.x * 128;

    float c[4][4][4];
#pragma unroll
    for (int mi = 0; mi < 4; mi++)
#pragma unroll
        for (int ni = 0; ni < 4; ni++)
#pragma unroll
            for (int r = 0; r < 4; r++) c[mi][ni][r] = 0.f;

    for (int phase = 0; phase < 2; ++phase) {
        const float* A = phase ? MEAN : X;
        const float* W = phase ? Wn : Ws;

        float4 pa[4], pb[4];
#pragma unroll
        for (int i = 0; i < 4; i++) {
            int slot = tid + 256 * i;
            int r    = slot >> 3;
            int kq   = slot & 7;
            int grow = bm + r;
            pa[i] = make_float4(0.f, 0.f, 0.f, 0.f);
            if (grow < N_NODES)
                pa[i] = *(const float4*)&A[(size_t)grow * F + kq * 4];
            int kr = slot >> 5;
            int nb = (slot & 31) * 4;
            pb[i] = *(const float4*)&W[(size_t)kr * F + nb];
        }

        for (int kc = 0; kc < 4; ++kc) {
#pragma unroll
            for (int i = 0; i < 4; i++) {
                int slot = tid + 256 * i;
                int r    = slot >> 3;
                int kq   = slot & 7;
                uint32_t* p = &As[r * PADA + kq * 4];
                p[0] = f2tf(pa[i].x); p[1] = f2tf(pa[i].y);
                p[2] = f2tf(pa[i].z); p[3] = f2tf(pa[i].w);
                int kr = slot >> 5;
                int nb = (slot & 31) * 4;
                uint32_t* q = &Bs[kr * PADB + nb];
                q[0] = f2tf(pb[i].x); q[1] = f2tf(pb[i].y);
                q[2] = f2tf(pb[i].z); q[3] = f2tf(pb[i].w);
            }
            __syncthreads();

            if (kc < 3) {
                const int k0n = (kc + 1) * 32;
#pragma unroll
                for (int i = 0; i < 4; i++) {
                    int slot = tid + 256 * i;
                    int r    = slot >> 3;
                    int kq   = slot & 7;
                    int grow = bm + r;
                    pa[i] = make_float4(0.f, 0.f, 0.f, 0.f);
                    if (grow < N_NODES)
                        pa[i] = *(const float4*)&A[(size_t)grow * F + k0n + kq * 4];
                    int kr = slot >> 5;
                    int nb = (slot & 31) * 4;
                    pb[i] = *(const float4*)&W[(size_t)(k0n + kr) * F + nb];
                }
            }

#pragma unroll
            for (int ks = 0; ks < 4; ++ks) {
                uint32_t a[4][4];
                uint32_t b[4][2];
#pragma unroll
                for (int mi = 0; mi < 4; mi++) {
                    int r0 = wm * 64 + mi * 16 + g;
                    a[mi][0] = As[r0 * PADA + ks * 8 + tig];
                    a[mi][1] = As[(r0 + 8) * PADA + ks * 8 + tig];
                    a[mi][2] = As[r0 * PADA + ks * 8 + tig + 4];
                    a[mi][3] = As[(r0 + 8) * PADA + ks * 8 + tig + 4];
                }
#pragma unroll
                for (int ni = 0; ni < 4; ni++) {
                    int cb = wn * 32 + ni * 8 + g;
                    b[ni][0] = Bs[(ks * 8 + tig) * PADB + cb];
                    b[ni][1] = Bs[(ks * 8 + tig + 4) * PADB + cb];
                }
#pragma unroll
                for (int mi = 0; mi < 4; mi++)
#pragma unroll
                    for (int ni = 0; ni < 4; ni++)
                        mma_tf32(c[mi][ni], a[mi], b[ni]);
            }
            __syncthreads();
        }
    }

    // ---- epilogue: bias (+relu), fp32 stores (+ optional fp16 mirror)
#pragma unroll
    for (int mi = 0; mi < 4; mi++) {
        int row0 = bm + wm * 64 + mi * 16 + g;
#pragma unroll
        for (int ni = 0; ni < 4; ni++) {
            int col = wn * 32 + ni * 8 + tig * 2;
            float2 bb = *(const float2*)&bias[col];
            float2 o0, o1;
            o0.x = c[mi][ni][0] + bb.x;
            o0.y = c[mi][ni][1] + bb.y;
            o1.x = c[mi][ni][2] + bb.x;
            o1.y = c[mi][ni][3] + bb.y;
            if (do_relu) {
                o0.x = fmaxf(o0.x, 0.f); o0.y = fmaxf(o0.y, 0.f);
                o1.x = fmaxf(o1.x, 0.f); o1.y = fmaxf(o1.y, 0.f);
            }
            if (row0 < N_NODES) {
                *(float2*)&out[(size_t)row0 * F + col] = o0;
                if (out16)
                    *(__half2*)&out16[(size_t)row0 * F + col] = __floats2half2_rn(o0.x, o0.y);
            }
            if (row0 + 8 < N_NODES) {
                *(float2*)&out[(size_t)(row0 + 8) * F + col] = o1;
                if (out16)
                    *(__half2*)&out16[(size_t)(row0 + 8) * F + col] = __floats2half2_rn(o1.x, o1.y);
            }
        }
    }
}

// ---------------- launch ----------------------------------------------------
extern "C" void kernel_launch(void* const* d_in, const int* in_sizes, int n_in,
                              void* d_out, int out_size)
{
    const float* feat = (const float*)d_in[0];
    const int*   src  = (const int*)d_in[1];
    const int*   dst  = (const int*)d_in[2];
    const float* W1s = (const float*)d_in[3];
    const float* W1n = (const float*)d_in[4];
    const float* b1  = (const float*)d_in[5];
    const float* W2s = (const float*)d_in[6];
    const float* W2n = (const float*)d_in[7];
    const float* b2  = (const float*)d_in[8];
    const float* W3s = (const float*)d_in[9];
    const float* W3n = (const float*)d_in[10];
    const float* b3  = (const float*)d_in[11];
    float* out = (float*)d_out;

    void* p;
    cudaGetSymbolAddress(&p, g_h1);     float*  h1   = (float*)p;
    cudaGetSymbolAddress(&p, g_h2);     float*  h2   = (float*)p;
    cudaGetSymbolAddress(&p, g_mean);   float*  mean = (float*)p;
    cudaGetSymbolAddress(&p, g_x16);    __half* x16  = (__half*)p;
    cudaGetSymbolAddress(&p, g_cursor); int*    cur  = (int*)p;

    const int TB = 256;
    const int agg_grid  = (N_NODES + 7) / 8;
    const int gemm_grid = (N_NODES + 127) / 128;

    // CSR build (+ fp16 convert of layer-1 input)
    cudaMemsetAsync(cur, 0, N_NODES * sizeof(int), 0);
    convert_kernel<<<(N_NODES * F / 4 + TB - 1) / TB, TB>>>(feat, x16);
    count_kernel<<<(N_EDGES + TB - 1) / TB, TB>>>(dst);
    scanA_kernel<<<NB_SCAN, 256>>>();
    scanB_kernel<<<1, 256>>>();
    scanC_kernel<<<NB_SCAN, 256>>>();
    fill_kernel<<<(N_EDGES + TB - 1) / TB, TB>>>(src, dst);

    // layer 1
    aggregate16_kernel<<<agg_grid, TB>>>(x16);
    gemm_sage_tf32<<<gemm_grid, TB>>>(feat, mean, W1s, W1n, b1, h1, x16, 1);
    // layer 2
    aggregate16_kernel<<<agg_grid, TB>>>(x16);
    gemm_sage_tf32<<<gemm_grid, TB>>>(h1, mean, W2s, W2n, b2, h2, x16, 1);
    // layer 3
    aggregate16_kernel<<<agg_grid, TB>>>(x16);
    gemm_sage_tf32<<<gemm_grid, TB>>>(h2, mean, W3s, W3n, b3, out, nullptr, 0);
}

// round 10
// speedup vs baseline: 1.2270x; 1.1031x over previous
#include <cuda_runtime.h>
#include <cuda_bf16.h>
#include <cstdint>

#define N_NODES 50000
#define N_EDGES 600000
#define F 128
#define NB_SCAN 196   // ceil(50000/256)

// ---------------- scratch (static device globals; no runtime allocation) ----
__device__ float g_mean[N_NODES * F];
__device__ float g_h1[N_NODES * F];
__device__ float g_h2[N_NODES * F];
__device__ int   g_rowptr[N_NODES + 1];
__device__ int   g_cursor[N_NODES];
__device__ float g_invdeg[N_NODES];
__device__ int   g_csrsrc[N_EDGES];
__device__ int   g_bsum[NB_SCAN];
__device__ int   g_boff[NB_SCAN];

// ---------------- CSR build -------------------------------------------------
// Vectorized count: int4 loads, 4 atomics per thread (600000 % 4 == 0).
__global__ void count_kernel(const int* __restrict__ dst) {
    int i = blockIdx.x * blockDim.x + threadIdx.x;
    if (i < N_EDGES / 4) {
        int4 d = *(const int4*)&dst[i * 4];
        atomicAdd(&g_cursor[d.x], 1);
        atomicAdd(&g_cursor[d.y], 1);
        atomicAdd(&g_cursor[d.z], 1);
        atomicAdd(&g_cursor[d.w], 1);
    }
}

// Parallel scan: A (block-local) -> B (block sums) -> C (apply)
__global__ void scanA_kernel() {
    int i = blockIdx.x * 256 + threadIdx.x;
    int c = (i < N_NODES) ? g_cursor[i] : 0;
    __shared__ int s[256];
    s[threadIdx.x] = c;
    __syncthreads();
#pragma unroll
    for (int off = 1; off < 256; off <<= 1) {
        int v = (threadIdx.x >= off) ? s[threadIdx.x - off] : 0;
        __syncthreads();
        s[threadIdx.x] += v;
        __syncthreads();
    }
    int incl = s[threadIdx.x];
    if (i < N_NODES) {
        g_rowptr[i] = incl - c;
        g_invdeg[i] = 1.0f / (float)(c > 1 ? c : 1);
    }
    if (threadIdx.x == 255) g_bsum[blockIdx.x] = incl;
}

__global__ void scanB_kernel() {
    int b = threadIdx.x;
    int v = (b < NB_SCAN) ? g_bsum[b] : 0;
    __shared__ int s[256];
    s[b] = v;
    __syncthreads();
#pragma unroll
    for (int off = 1; off < 256; off <<= 1) {
        int w = (b >= off) ? s[b - off] : 0;
        __syncthreads();
        s[b] += w;
        __syncthreads();
    }
    if (b < NB_SCAN) g_boff[b] = s[b] - v;
    if (b == 0) g_rowptr[N_NODES] = s[NB_SCAN - 1];
}

__global__ void scanC_kernel() {
    int i = blockIdx.x * 256 + threadIdx.x;
    if (i < N_NODES) {
        int r = g_rowptr[i] + g_boff[blockIdx.x];
        g_rowptr[i] = r;
        g_cursor[i] = r;
    }
}

// Vectorized fill: int4 loads of src and dst.
__global__ void fill_kernel(const int* __restrict__ src, const int* __restrict__ dst) {
    int i = blockIdx.x * blockDim.x + threadIdx.x;
    if (i < N_EDGES / 4) {
        int4 d = *(const int4*)&dst[i * 4];
        int4 s = *(const int4*)&src[i * 4];
        g_csrsrc[atomicAdd(&g_cursor[d.x], 1)] = s.x;
        g_csrsrc[atomicAdd(&g_cursor[d.y], 1)] = s.y;
        g_csrsrc[atomicAdd(&g_cursor[d.z], 1)] = s.z;
        g_csrsrc[atomicAdd(&g_cursor[d.w], 1)] = s.w;
    }
}

// ---------------- neighbor mean aggregation (warp per node, no atomics) -----
__global__ void aggregate_kernel(const float* __restrict__ x) {
    int warp = (blockIdx.x * blockDim.x + threadIdx.x) >> 5;
    int lane = threadIdx.x & 31;
    if (warp >= N_NODES) return;

    int beg = g_rowptr[warp];
    int end = g_rowptr[warp + 1];

    float4 acc = make_float4(0.f, 0.f, 0.f, 0.f);
    for (int i = beg; i < end; i++) {
        int s = __ldg(&g_csrsrc[i]);
        float4 v = *(const float4*)&x[(size_t)s * F + lane * 4];
        acc.x += v.x; acc.y += v.y; acc.z += v.z; acc.w += v.w;
    }
    float inv = g_invdeg[warp];
    float4 o = make_float4(acc.x * inv, acc.y * inv, acc.z * inv, acc.w * inv);
    *(float4*)&g_mean[(size_t)warp * F + lane * 4] = o;
}

// ---------------- tf32 helpers ----------------------------------------------
__device__ __forceinline__ uint32_t f2tf(float x) {
    uint32_t r;
    asm("cvt.rna.tf32.f32 %0, %1;" : "=r"(r) : "f"(x));
    return r;
}

__device__ __forceinline__ void mma_tf32(float* c, const uint32_t* a, const uint32_t* b) {
    asm volatile(
        "mma.sync.aligned.m16n8k8.row.col.f32.tf32.tf32.f32 "
        "{%0,%1,%2,%3}, {%4,%5,%6,%7}, {%8,%9}, {%0,%1,%2,%3};"
        : "+f"(c[0]), "+f"(c[1]), "+f"(c[2]), "+f"(c[3])
        : "r"(a[0]), "r"(a[1]), "r"(a[2]), "r"(a[3]),
          "r"(b[0]), "r"(b[1]));
}

#define PADA 36
#define PADB 136

// out[M,128] = X @ Ws + mean @ Wn + b (optional relu)
// Block tile 128x128, BK=32, 8 warps (2m x 4n), m16n8k8 tf32.
// Global->register prefetch of the next k-chunk overlaps gmem latency with MMA.
__global__ __launch_bounds__(256, 2) void gemm_sage_tf32(
    const float* __restrict__ X,
    const float* __restrict__ MEAN,
    const float* __restrict__ Ws, const float* __restrict__ Wn,
    const float* __restrict__ bias,
    float* __restrict__ out, int do_relu)
{
    __shared__ uint32_t As[128 * PADA];  // 18432 B
    __shared__ uint32_t Bs[32 * PADB];   // 17408 B

    const int tid  = threadIdx.x;
    const int lane = tid & 31;
    const int wid  = tid >> 5;
    const int wm   = wid & 1;
    const int wn   = wid >> 1;
    const int g    = lane >> 2;
    const int tig  = lane & 3;
    const int bm   = blockIdx.x * 128;

    float c[4][4][4];
#pragma unroll
    for (int mi = 0; mi < 4; mi++)
#pragma unroll
        for (int ni = 0; ni < 4; ni++)
#pragma unroll
            for (int r = 0; r < 4; r++) c[mi][ni][r] = 0.f;

    for (int phase = 0; phase < 2; ++phase) {
        const float* A = phase ? MEAN : X;
        const float* W = phase ? Wn : Ws;

        float4 pa[4], pb[4];
        // preload chunk 0
#pragma unroll
        for (int i = 0; i < 4; i++) {
            int slot = tid + 256 * i;
            int r    = slot >> 3;
            int kq   = slot & 7;
            int grow = bm + r;
            pa[i] = make_float4(0.f, 0.f, 0.f, 0.f);
            if (grow < N_NODES)
                pa[i] = *(const float4*)&A[(size_t)grow * F + kq * 4];
            int kr = slot >> 5;
            int nb = (slot & 31) * 4;
            pb[i] = *(const float4*)&W[(size_t)kr * F + nb];
        }

        for (int kc = 0; kc < 4; ++kc) {
            // commit prefetched chunk to smem
#pragma unroll
            for (int i = 0; i < 4; i++) {
                int slot = tid + 256 * i;
                int r    = slot >> 3;
                int kq   = slot & 7;
                uint32_t* p = &As[r * PADA + kq * 4];
                p[0] = f2tf(pa[i].x); p[1] = f2tf(pa[i].y);
                p[2] = f2tf(pa[i].z); p[3] = f2tf(pa[i].w);
                int kr = slot >> 5;
                int nb = (slot & 31) * 4;
                uint32_t* q = &Bs[kr * PADB + nb];
                q[0] = f2tf(pb[i].x); q[1] = f2tf(pb[i].y);
                q[2] = f2tf(pb[i].z); q[3] = f2tf(pb[i].w);
            }
            __syncthreads();

            // prefetch next chunk (gmem latency hides under MMA below)
            if (kc < 3) {
                const int k0n = (kc + 1) * 32;
#pragma unroll
                for (int i = 0; i < 4; i++) {
                    int slot = tid + 256 * i;
                    int r    = slot >> 3;
                    int kq   = slot & 7;
                    int grow = bm + r;
                    pa[i] = make_float4(0.f, 0.f, 0.f, 0.f);
                    if (grow < N_NODES)
                        pa[i] = *(const float4*)&A[(size_t)grow * F + k0n + kq * 4];
                    int kr = slot >> 5;
                    int nb = (slot & 31) * 4;
                    pb[i] = *(const float4*)&W[(size_t)(k0n + kr) * F + nb];
                }
            }

#pragma unroll
            for (int ks = 0; ks < 4; ++ks) {
                uint32_t a[4][4];
                uint32_t b[4][2];
#pragma unroll
                for (int mi = 0; mi < 4; mi++) {
                    int r0 = wm * 64 + mi * 16 + g;
                    a[mi][0] = As[r0 * PADA + ks * 8 + tig];
                    a[mi][1] = As[(r0 + 8) * PADA + ks * 8 + tig];
                    a[mi][2] = As[r0 * PADA + ks * 8 + tig + 4];
                    a[mi][3] = As[(r0 + 8) * PADA + ks * 8 + tig + 4];
                }
#pragma unroll
                for (int ni = 0; ni < 4; ni++) {
                    int cb = wn * 32 + ni * 8 + g;
                    b[ni][0] = Bs[(ks * 8 + tig) * PADB + cb];
                    b[ni][1] = Bs[(ks * 8 + tig + 4) * PADB + cb];
                }
#pragma unroll
                for (int mi = 0; mi < 4; mi++)
#pragma unroll
                    for (int ni = 0; ni < 4; ni++)
                        mma_tf32(c[mi][ni], a[mi], b[ni]);
            }
            __syncthreads();
        }
    }

    // ---- epilogue: bias (+relu), float2 stores
#pragma unroll
    for (int mi = 0; mi < 4; mi++) {
        int row0 = bm + wm * 64 + mi * 16 + g;
#pragma unroll
        for (int ni = 0; ni < 4; ni++) {
            int col = wn * 32 + ni * 8 + tig * 2;
            float2 bb = *(const float2*)&bias[col];
            float2 o0, o1;
            o0.x = c[mi][ni][0] + bb.x;
            o0.y = c[mi][ni][1] + bb.y;
            o1.x = c[mi][ni][2] + bb.x;
            o1.y = c[mi][ni][3] + bb.y;
            if (do_relu) {
                o0.x = fmaxf(o0.x, 0.f); o0.y = fmaxf(o0.y, 0.f);
                o1.x = fmaxf(o1.x, 0.f); o1.y = fmaxf(o1.y, 0.f);
            }
            if (row0 < N_NODES)
                *(float2*)&out[(size_t)row0 * F + col] = o0;
            if (row0 + 8 < N_NODES)
                *(float2*)&out[(size_t)(row0 + 8) * F + col] = o1;
        }
    }
}

// ---------------- launch ----------------------------------------------------
extern "C" void kernel_launch(void* const* d_in, const int* in_sizes, int n_in,
                              void* d_out, int out_size)
{
    const float* feat = (const float*)d_in[0];
    const int*   src  = (const int*)d_in[1];
    const int*   dst  = (const int*)d_in[2];
    const float* W1s = (const float*)d_in[3];
    const float* W1n = (const float*)d_in[4];
    const float* b1  = (const float*)d_in[5];
    const float* W2s = (const float*)d_in[6];
    const float* W2n = (const float*)d_in[7];
    const float* b2  = (const float*)d_in[8];
    const float* W3s = (const float*)d_in[9];
    const float* W3n = (const float*)d_in[10];
    const float* b3  = (const float*)d_in[11];
    float* out = (float*)d_out;

    void* p;
    cudaGetSymbolAddress(&p, g_h1);     float* h1   = (float*)p;
    cudaGetSymbolAddress(&p, g_h2);     float* h2   = (float*)p;
    cudaGetSymbolAddress(&p, g_mean);   float* mean = (float*)p;
    cudaGetSymbolAddress(&p, g_cursor); int*   cur  = (int*)p;

    const int TB = 256;
    // CSR build (memset node + vectorized count/fill + parallel scan)
    cudaMemsetAsync(cur, 0, N_NODES * sizeof(int), 0);
    count_kernel<<<(N_EDGES / 4 + TB - 1) / TB, TB>>>(dst);
    scanA_kernel<<<NB_SCAN, 256>>>();
    scanB_kernel<<<1, 256>>>();
    scanC_kernel<<<NB_SCAN, 256>>>();
    fill_kernel<<<(N_EDGES / 4 + TB - 1) / TB, TB>>>(src, dst);

    const int agg_grid  = (N_NODES + 7) / 8;      // 8 warps/block
    const int gemm_grid = (N_NODES + 127) / 128;  // 391

    // layer 1
    aggregate_kernel<<<agg_grid, TB>>>(feat);
    gemm_sage_tf32<<<gemm_grid, TB>>>(feat, mean, W1s, W1n, b1, h1, 1);
    // layer 2
    aggregate_kernel<<<agg_grid, TB>>>(h1);
    gemm_sage_tf32<<<gemm_grid, TB>>>(h1, mean, W2s, W2n, b2, h2, 1);
    // layer 3
    aggregate_kernel<<<agg_grid, TB>>>(h2);
    gemm_sage_tf32<<<gemm_grid, TB>>>(h2, mean, W3s, W3n, b3, out, 0);
}